// round 9
// baseline (speedup 1.0000x reference)
#include <cuda_runtime.h>
#include <cuda_bf16.h>
#include <math.h>

// Problem constants
#define BB 32
#define LL 1024
#define XX 1024
#define YY 1024
#define AA 16
#define MM 48          // 16 action rows + 32 batch rows
#define MSPLIT 2
#define MH (MM / MSPLIT)   // 24 rows per m-split (measured-best k1 shape)
#define YT 64          // number of Y tiles in stage 1
#define YS (YY / YT)   // 16 y-rows per tile
#define K3S 8          // x-slices in k3 (blocks per batch)
#define K3W (XX / K3S) // 128 x per k3 block
#define RPB 16         // rows per block in k4 (1 row per warp, 16 warps)
#define BPB (LL / RPB) // 64 blocks per batch in k4

// Scratch (allocation-free: __device__ globals)
__device__ float g_part[YT][MM][XX];   // partial GEMM sums, 12 MB
__device__ float g_sa[BB][XX];         // score row (pre-softmax)
__device__ float g_sy[BB][XX];         // yW row
__device__ float g_wy[BB][XX];         // Wy[b,x]
__device__ float g_z[BB][LL];          // masked logits
__device__ float g_pm[BB][BPB];        // k4 per-block partial max
__device__ float g_ps[BB][BPB];        // k4 per-block partial sumexp
__device__ float g_pm3[BB][K3S];       // k3 per-block partial max
__device__ float g_ps3[BB][K3S];       // k3 per-block partial sumexp
__device__ int   g_cnt[BB];            // k4 arrival counters
__device__ int   g_cnt3[BB];           // k3 arrival counters

#define GDC_LAUNCH() asm volatile("griddepcontrol.launch_dependents;" ::: "memory")
#define GDC_WAIT()   asm volatile("griddepcontrol.wait;" ::: "memory")

__device__ __forceinline__ void lse_combine(float& m, float& s, float m2, float s2) {
    const float M = fmaxf(m, m2);
    s = s * __expf(m - M) + s2 * __expf(m2 - M);
    m = M;
}

// ---------------------------------------------------------------------------
// K1: partial skinny GEMM. g_part[yt][m][x] = sum_{y in tile} in[m,y]*W[y,x]
// grid (X/128, YT, MSPLIT=2), block 128. Thread owns one x column, 24 accs.
// ---------------------------------------------------------------------------
__global__ __launch_bounds__(128) void k1_partial_gemm(
    const float* __restrict__ wa_h,   // [A, Y]
    const float* __restrict__ y_in,   // [B, Y]
    const float* __restrict__ weight) // [Y, X]
{
    GDC_LAUNCH();   // let k3/k4 start early; they gate via gdc.wait
    __shared__ float in_s[YS * MH];
    const int x  = blockIdx.x * 128 + threadIdx.x;
    const int y0 = blockIdx.y * YS;
    const int m0 = blockIdx.z * MH;

    for (int i = threadIdx.x; i < YS * MH; i += 128) {
        const int yl = i / MH;
        const int m  = m0 + i % MH;
        float v;
        if (m < AA) v = wa_h[m * YY + (y0 + yl)];
        else        v = y_in[(m - AA) * YY + (y0 + yl)];
        in_s[i] = v;
    }
    __syncthreads();

    float acc[MH];
#pragma unroll
    for (int m = 0; m < MH; m++) acc[m] = 0.0f;

#pragma unroll 8
    for (int yl = 0; yl < YS; yl++) {
        const float w = weight[(size_t)(y0 + yl) * XX + x];
        const float4* r = reinterpret_cast<const float4*>(&in_s[yl * MH]);
#pragma unroll
        for (int q = 0; q < MH / 4; q++) {
            const float4 v = r[q];
            acc[4 * q + 0] = fmaf(w, v.x, acc[4 * q + 0]);
            acc[4 * q + 1] = fmaf(w, v.y, acc[4 * q + 1]);
            acc[4 * q + 2] = fmaf(w, v.z, acc[4 * q + 2]);
            acc[4 * q + 3] = fmaf(w, v.w, acc[4 * q + 3]);
        }
    }

#pragma unroll
    for (int m = 0; m < MH; m++)
        g_part[blockIdx.y][m0 + m][x] = acc[m];
}

// ---------------------------------------------------------------------------
// K3 wide: grid (BB, K3S=8), block 128. Slice reduces g_part for its 128 x,
// writes (sa, sy) + partial (max, sumexp); last block per b combines and
// writes Wy[b,:] = sy * exp(sa - lse) + bias.
// ---------------------------------------------------------------------------
__global__ __launch_bounds__(128) void k3_softmax_wy(
    const int* __restrict__ actions,
    const float* __restrict__ bias)
{
    GDC_LAUNCH();            // let k4 start early
    __shared__ float red[4];
    __shared__ float s_elect;
    const int b     = blockIdx.x;
    const int slice = blockIdx.y;
    const int tid   = threadIdx.x;
    const int warp  = tid >> 5;
    const int lane  = tid & 31;
    const int x     = slice * K3W + tid;

    GDC_WAIT();              // wait for k1 grid completion (acquire g_part)
    const int act = actions[b];

    float sa = 0.0f, sy = 0.0f;
#pragma unroll 8
    for (int yt = 0; yt < YT; yt++) {
        sa += g_part[yt][act][x];
        sy += g_part[yt][AA + b][x];
    }
    g_sa[b][x] = sa;
    g_sy[b][x] = sy;

    // block partial (m, s) over the 128 sa values
    float m = sa, s = 1.0f;
#pragma unroll
    for (int o = 16; o; o >>= 1) {
        float m2 = __shfl_xor_sync(0xffffffffu, m, o);
        float s2 = __shfl_xor_sync(0xffffffffu, s, o);
        lse_combine(m, s, m2, s2);
    }
    if (lane == 0) { red[warp] = m; ((float*)red)[warp] = m; }
    __shared__ float redm[4], reds[4];
    if (lane == 0) { redm[warp] = m; reds[warp] = s; }
    __syncthreads();
    if (tid == 0) {
        float M = redm[0], S = reds[0];
#pragma unroll
        for (int w = 1; w < 4; w++) lse_combine(M, S, redm[w], reds[w]);
        g_pm3[b][slice] = M;
        g_ps3[b][slice] = S;
    }
    __threadfence();
    __syncthreads();

    if (tid == 0) {
        const int old = atomicAdd(&g_cnt3[b], 1);
        s_elect = (old == K3S - 1) ? 1.0f : 0.0f;
    }
    __syncthreads();
    if (s_elect == 0.0f) return;

    // last block for batch b: combine partials, write Wy
    __threadfence();
    if (tid == 0) g_cnt3[b] = 0;     // reset for graph replay

    __shared__ float s_lse;
    if (tid == 0) {
        float M = g_pm3[b][0], S = g_ps3[b][0];
#pragma unroll
        for (int k = 1; k < K3S; k++) lse_combine(M, S, g_pm3[b][k], g_ps3[b][k]);
        s_lse = M + logf(S);
    }
    __syncthreads();
    const float lse = s_lse;

#pragma unroll
    for (int i = 0; i < K3S; i++) {
        const int xx = i * 128 + tid;
        g_wy[b][xx] = g_sy[b][xx] * __expf(g_sa[b][xx] - lse) + bias[xx];
    }
}

// ---------------------------------------------------------------------------
// K4 fused: z[b,l] = dot(x[b,l,:], Wy[b,:]) (mask -> -inf), then per-batch
// log_softmax by the last-arriving block per batch.
// grid (B, BPB=64), block 512: 16 warps x 1 row.
// PDL: blocks launch during k1/k3, prefetch their x rows, THEN wait for k3.
// ---------------------------------------------------------------------------
__global__ __launch_bounds__(512) void k4_fused(
    const float* __restrict__ x,
    const unsigned char* __restrict__ x_mask,
    float* __restrict__ out)
{
    __shared__ float4 wy_s[XX / 4];
    __shared__ float  zrow[RPB];
    __shared__ float  s_elect;
    __shared__ float  s_lse;
    const int b     = blockIdx.x;
    const int chunk = blockIdx.y;
    const int tid   = threadIdx.x;
    const int warp  = tid >> 5;
    const int lane  = tid & 31;

    const int l = chunk * RPB + warp;
    const float4* xr =
        reinterpret_cast<const float4*>(x + ((size_t)b * LL + l) * XX);

    // 1) issue x loads (independent of upstream kernels) — overlaps k1/k3
    float4 xv[8];
#pragma unroll
    for (int it = 0; it < 8; it++) xv[it] = xr[it * 32 + lane];
    const unsigned char mk = (lane == 0) ? x_mask[b * LL + l] : 0;

    // 2) wait for k3 grid (acquire g_wy), then stage Wy
    GDC_WAIT();
    for (int i = tid; i < XX / 4; i += 512)
        wy_s[i] = reinterpret_cast<const float4*>(&g_wy[b][0])[i];
    __syncthreads();

    // 3) compute
    float acc = 0.0f;
#pragma unroll
    for (int it = 0; it < 8; it++) {
        const float4 wv = wy_s[it * 32 + lane];
        acc = fmaf(xv[it].x, wv.x, acc);
        acc = fmaf(xv[it].y, wv.y, acc);
        acc = fmaf(xv[it].z, wv.z, acc);
        acc = fmaf(xv[it].w, wv.w, acc);
    }
#pragma unroll
    for (int o = 16; o; o >>= 1) acc += __shfl_xor_sync(0xffffffffu, acc, o);
    if (lane == 0)
        zrow[warp] = mk ? -INFINITY : acc;
    __syncthreads();

    // write z chunk + block partial (m, s)
    if (tid < RPB)
        g_z[b][chunk * RPB + tid] = zrow[tid];
    if (warp == 0 && lane < RPB) {
        float m = zrow[lane];
        float s = 1.0f;
#pragma unroll
        for (int o = 8; o; o >>= 1) {
            float m2 = __shfl_xor_sync(0xffffu, m, o);
            float s2 = __shfl_xor_sync(0xffffu, s, o);
            lse_combine(m, s, m2, s2);
        }
        if (lane == 0) {
            g_pm[b][chunk] = m;
            g_ps[b][chunk] = s;
        }
    }
    __threadfence();
    __syncthreads();

    if (tid == 0) {
        const int old = atomicAdd(&g_cnt[b], 1);
        s_elect = (old == BPB - 1) ? 1.0f : 0.0f;
    }
    __syncthreads();
    if (s_elect == 0.0f) return;

    // ---- last block for batch b: finish log_softmax ----
    __threadfence();
    if (tid == 0) g_cnt[b] = 0;      // reset for next graph replay

    if (warp == 0) {
        // combine BPB=64 partials: each lane owns 2
        float m = g_pm[b][lane];
        float s = g_ps[b][lane];
        lse_combine(m, s, g_pm[b][lane + 32], g_ps[b][lane + 32]);
#pragma unroll
        for (int o = 16; o; o >>= 1) {
            float m2 = __shfl_xor_sync(0xffffffffu, m, o);
            float s2 = __shfl_xor_sync(0xffffffffu, s, o);
            lse_combine(m, s, m2, s2);
        }
        if (lane == 0) s_lse = m + logf(s);
    }
    __syncthreads();
    const float lse = s_lse;

    const float4* zr = reinterpret_cast<const float4*>(&g_z[b][0]);
    float4*       po = reinterpret_cast<float4*>(out + b * LL);
    for (int i = tid; i < LL / 4; i += 512) {
        float4 z = zr[i];
        po[i] = make_float4(z.x - lse, z.y - lse, z.z - lse, z.w - lse);
    }
}

// ---------------------------------------------------------------------------
// Launch. Input order: x, y, x_mask, actions, weight, bias, wa_h
// PDL chain k1 -> k3 -> k4: prologues overlap upstream kernels.
// ---------------------------------------------------------------------------
extern "C" void kernel_launch(void* const* d_in, const int* in_sizes, int n_in,
                              void* d_out, int out_size)
{
    const float*         x       = (const float*)d_in[0];
    const float*         y_in    = (const float*)d_in[1];
    const unsigned char* x_mask  = (const unsigned char*)d_in[2];
    const int*           actions = (const int*)d_in[3];
    const float*         weight  = (const float*)d_in[4];
    const float*         bias    = (const float*)d_in[5];
    const float*         wa_h    = (const float*)d_in[6];
    float*               out     = (float*)d_out;

    k1_partial_gemm<<<dim3(XX / 128, YT, MSPLIT), 128>>>(wa_h, y_in, weight);

    cudaLaunchAttribute pdl[1];
    pdl[0].id = cudaLaunchAttributeProgrammaticStreamSerialization;
    pdl[0].val.programmaticStreamSerializationAllowed = 1;

    {
        cudaLaunchConfig_t cfg = {};
        cfg.gridDim  = dim3(BB, K3S);
        cfg.blockDim = dim3(128);
        cfg.attrs    = pdl;
        cfg.numAttrs = 1;
        cudaLaunchKernelEx(&cfg, k3_softmax_wy, actions, bias);
    }
    {
        cudaLaunchConfig_t cfg = {};
        cfg.gridDim  = dim3(BB, BPB);
        cfg.blockDim = dim3(512);
        cfg.attrs    = pdl;
        cfg.numAttrs = 1;
        cudaLaunchKernelEx(&cfg, k4_fused, x, x_mask, out);
    }
}